// round 1
// baseline (speedup 1.0000x reference)
#include <cuda_runtime.h>

#define HW   96
#define LDP  100      // padded row stride (floats); row base = 400B, 16B aligned
#define TS   6        // per-thread tile edge

// Load 6 consecutive floats via 3x float2 (8B alignment always holds: col = 6*tx)
#define LOAD6(dst, ptr) do {                              \
    float2 _t0 = *(const float2*)((ptr));                 \
    float2 _t1 = *(const float2*)((ptr) + 2);             \
    float2 _t2 = *(const float2*)((ptr) + 4);             \
    (dst)[0] = _t0.x; (dst)[1] = _t0.y;                   \
    (dst)[2] = _t1.x; (dst)[3] = _t1.y;                   \
    (dst)[4] = _t2.x; (dst)[5] = _t2.y;                   \
} while (0)

__global__ void __launch_bounds__(256, 1)
axial_attn_kernel(const float* __restrict__ gq, const float* __restrict__ gk,
                  const float* __restrict__ gv, const float* __restrict__ gkh,
                  const float* __restrict__ gkw, float* __restrict__ gout, int C)
{
    extern __shared__ float sm[];
    float* sQ  = sm;                 // 96 x 100
    float* sK  = sQ + HW * LDP;      // 96 x 100
    float* sV  = sK + HW * LDP;      // 96 x 100  (V, later V1)
    float* sA  = sV + HW * LDP;      // 96 x 100  (A1, later A2^T)
    float* sKH = sA + HW * LDP;      // 16
    float* sKW = sKH + 16;           // 16

    const int tid = threadIdx.x;
    const int tx  = tid & 15;        // lane-contiguous 16-group
    const int ty  = tid >> 4;
    const int i0  = ty * TS;         // register-tile row origin
    const int j0  = tx * TS;         // register-tile col origin

    const int slice = blockIdx.x;
    const int c = slice - (slice / C) * C;

    const size_t base = (size_t)slice * (HW * HW);
    const float4* q4 = (const float4*)(gq + base);
    const float4* k4 = (const float4*)(gk + base);
    const float4* v4 = (const float4*)(gv + base);

    // ---- Stage 0: load Q, K, V tiles (float4, coalesced) + kernel rows ----
    #pragma unroll
    for (int f = tid; f < HW * HW / 4; f += 256) {
        int row = f / (HW / 4);
        int col = (f - row * (HW / 4)) * 4;
        int so  = row * LDP + col;
        *(float4*)(sQ + so) = q4[f];
        *(float4*)(sK + so) = k4[f];
        *(float4*)(sV + so) = v4[f];
    }
    if (tid < 13) {
        sKH[tid] = gkh[c * 13 + tid];
        sKW[tid] = gkw[c * 13 + tid];
    }
    __syncthreads();

    float acc[TS][TS];

    // ================= GEMM 1: S1 = Q * K^T (both k-fast, float4) ==========
    #pragma unroll
    for (int r = 0; r < TS; r++)
        #pragma unroll
        for (int cc = 0; cc < TS; cc++) acc[r][cc] = 0.f;

    #pragma unroll 2
    for (int kk = 0; kk < HW; kk += 4) {
        float4 a[TS], b[TS];
        #pragma unroll
        for (int r = 0; r < TS; r++)  a[r] = *(const float4*)(sQ + (i0 + r) * LDP + kk);
        #pragma unroll
        for (int cc = 0; cc < TS; cc++) b[cc] = *(const float4*)(sK + (j0 + cc) * LDP + kk);
        #pragma unroll
        for (int r = 0; r < TS; r++)
            #pragma unroll
            for (int cc = 0; cc < TS; cc++) {
                acc[r][cc] = fmaf(a[r].x, b[cc].x, acc[r][cc]);
                acc[r][cc] = fmaf(a[r].y, b[cc].y, acc[r][cc]);
                acc[r][cc] = fmaf(a[r].z, b[cc].z, acc[r][cc]);
                acc[r][cc] = fmaf(a[r].w, b[cc].w, acc[r][cc]);
            }
    }

    // ---- Softmax (rows = h) + band_h; write A1 to sA (row-major) ----------
    #pragma unroll
    for (int r = 0; r < TS; r++) {
        float m = acc[r][0];
        #pragma unroll
        for (int cc = 1; cc < TS; cc++) m = fmaxf(m, acc[r][cc]);
        #pragma unroll
        for (int off = 8; off >= 1; off >>= 1)
            m = fmaxf(m, __shfl_xor_sync(0xffffffffu, m, off));
        float s = 0.f;
        #pragma unroll
        for (int cc = 0; cc < TS; cc++) {
            float e = __expf(acc[r][cc] - m);
            acc[r][cc] = e;
            s += e;
        }
        #pragma unroll
        for (int off = 8; off >= 1; off >>= 1)
            s += __shfl_xor_sync(0xffffffffu, s, off);
        float inv = 1.0f / s;
        const int i = i0 + r;
        #pragma unroll
        for (int cc = 0; cc < TS; cc++) {
            int j   = j0 + cc;
            int bo  = j - i + 6;
            float band = (bo >= 0 && bo < 13) ? sKH[bo] : 0.f;
            sA[i * LDP + j] = fmaf(acc[r][cc], inv, band);
        }
    }
    __syncthreads();

    // ================= GEMM 2: V1 = A1 * V (A k-fast, V k-slow) ============
    #pragma unroll
    for (int r = 0; r < TS; r++)
        #pragma unroll
        for (int cc = 0; cc < TS; cc++) acc[r][cc] = 0.f;

    #pragma unroll 2
    for (int kk = 0; kk < HW; kk += 4) {
        float4 a[TS];
        #pragma unroll
        for (int r = 0; r < TS; r++) a[r] = *(const float4*)(sA + (i0 + r) * LDP + kk);
        float b[4][TS];
        #pragma unroll
        for (int u = 0; u < 4; u++) LOAD6(b[u], sV + (kk + u) * LDP + j0);
        #pragma unroll
        for (int r = 0; r < TS; r++)
            #pragma unroll
            for (int cc = 0; cc < TS; cc++) {
                acc[r][cc] = fmaf(a[r].x, b[0][cc], acc[r][cc]);
                acc[r][cc] = fmaf(a[r].y, b[1][cc], acc[r][cc]);
                acc[r][cc] = fmaf(a[r].z, b[2][cc], acc[r][cc]);
                acc[r][cc] = fmaf(a[r].w, b[3][cc], acc[r][cc]);
            }
    }
    __syncthreads();   // everyone done reading sV and sA

    // overwrite sV with V1 (register -> smem)
    #pragma unroll
    for (int r = 0; r < TS; r++)
        #pragma unroll
        for (int cc = 0; cc < TS; cc++)
            sV[(i0 + r) * LDP + j0 + cc] = acc[r][cc];

    // ================= GEMM 3: S2 = Q^T * K (both k-slow, row loads) =======
    #pragma unroll
    for (int r = 0; r < TS; r++)
        #pragma unroll
        for (int cc = 0; cc < TS; cc++) acc[r][cc] = 0.f;

    #pragma unroll 4
    for (int h = 0; h < HW; h++) {
        float a6[TS], b6[TS];
        LOAD6(a6, sQ + h * LDP + i0);   // Q[h][w0..w5]  (broadcast across tx)
        LOAD6(b6, sK + h * LDP + j0);   // K[h][j0..j5]  (conflict-free)
        #pragma unroll
        for (int r = 0; r < TS; r++)
            #pragma unroll
            for (int cc = 0; cc < TS; cc++)
                acc[r][cc] = fmaf(a6[r], b6[cc], acc[r][cc]);
    }

    // ---- Softmax (rows = w) + band_w; write A2^T to sA:  sA[j][w] ---------
    #pragma unroll
    for (int r = 0; r < TS; r++) {
        float m = acc[r][0];
        #pragma unroll
        for (int cc = 1; cc < TS; cc++) m = fmaxf(m, acc[r][cc]);
        #pragma unroll
        for (int off = 8; off >= 1; off >>= 1)
            m = fmaxf(m, __shfl_xor_sync(0xffffffffu, m, off));
        float s = 0.f;
        #pragma unroll
        for (int cc = 0; cc < TS; cc++) {
            float e = __expf(acc[r][cc] - m);
            acc[r][cc] = e;
            s += e;
        }
        #pragma unroll
        for (int off = 8; off >= 1; off >>= 1)
            s += __shfl_xor_sync(0xffffffffu, s, off);
        float inv = 1.0f / s;
        const int w = i0 + r;
        #pragma unroll
        for (int cc = 0; cc < TS; cc++) {
            int j  = j0 + cc;
            int bo = j - w + 6;
            float band = (bo >= 0 && bo < 13) ? sKW[bo] : 0.f;
            sA[j * LDP + w] = fmaf(acc[r][cc], inv, band);   // transposed store
        }
    }
    __syncthreads();   // V1 and A2^T both visible

    // ================= GEMM 4: Out = V1 * A2^T  (both k-fast now) ==========
    #pragma unroll
    for (int r = 0; r < TS; r++)
        #pragma unroll
        for (int cc = 0; cc < TS; cc++) acc[r][cc] = 0.f;

    #pragma unroll 2
    for (int kk = 0; kk < HW; kk += 4) {
        float4 a[TS];
        #pragma unroll
        for (int r = 0; r < TS; r++) a[r] = *(const float4*)(sV + (i0 + r) * LDP + kk);
        float b[4][TS];
        #pragma unroll
        for (int u = 0; u < 4; u++) LOAD6(b[u], sA + (kk + u) * LDP + j0);
        #pragma unroll
        for (int r = 0; r < TS; r++)
            #pragma unroll
            for (int cc = 0; cc < TS; cc++) {
                acc[r][cc] = fmaf(a[r].x, b[0][cc], acc[r][cc]);
                acc[r][cc] = fmaf(a[r].y, b[1][cc], acc[r][cc]);
                acc[r][cc] = fmaf(a[r].z, b[2][cc], acc[r][cc]);
                acc[r][cc] = fmaf(a[r].w, b[3][cc], acc[r][cc]);
            }
    }

    // ---- Store Out (float2, coalesced enough) -----------------------------
    float* op = gout + base;
    #pragma unroll
    for (int r = 0; r < TS; r++) {
        float* orow = op + (i0 + r) * HW + j0;
        *(float2*)(orow + 0) = make_float2(acc[r][0], acc[r][1]);
        *(float2*)(orow + 2) = make_float2(acc[r][2], acc[r][3]);
        *(float2*)(orow + 4) = make_float2(acc[r][4], acc[r][5]);
    }
}

extern "C" void kernel_launch(void* const* d_in, const int* in_sizes, int n_in,
                              void* d_out, int out_size)
{
    const float* q  = (const float*)d_in[0];
    const float* k  = (const float*)d_in[1];
    const float* v  = (const float*)d_in[2];
    const float* kh = (const float*)d_in[3];
    const float* kw = (const float*)d_in[4];
    float* out = (float*)d_out;

    const int slices = in_sizes[0] / (HW * HW);   // B*C = 2048
    const int C      = in_sizes[3] / 13;          // 256

    const int smem_bytes = (4 * HW * LDP + 32) * (int)sizeof(float);  // 153728 B
    cudaFuncSetAttribute(axial_attn_kernel,
                         cudaFuncAttributeMaxDynamicSharedMemorySize, smem_bytes);

    axial_attn_kernel<<<slices, 256, smem_bytes>>>(q, k, v, kh, kw, out, C);
}